// round 2
// baseline (speedup 1.0000x reference)
#include <cuda_runtime.h>
#include <cstdint>
#include <math.h>

// Problem constants
#define KB  2
#define KH  16
#define KSQ 2048
#define KSK 2048
#define KD  64
#define KDV 64

#define TQ 64
#define TK 64
#define NT 256
#define QROW4 17   // padded row stride (in float4) for Q and P tiles = 68 floats

// smem layout (floats): Q [2*64][68] = 8704 | K [64][16f4 swizzled] = 4096
//                       V [64][16f4] = 4096 | P [2*64][68] = 8704
#define SM_Q 0
#define SM_K 8704
#define SM_V 12800
#define SM_P 16896
#define SM_TOTAL_FLOATS 25600   // 102400 bytes

// ---------------- packed f32x2 helpers (sm_103a FFMA2 path) ----------------
__device__ __forceinline__ unsigned long long pk2(float lo, float hi) {
    unsigned long long r;
    asm("mov.b64 %0, {%1, %2};" : "=l"(r) : "f"(lo), "f"(hi));
    return r;
}
__device__ __forceinline__ void upk2(unsigned long long v, float& lo, float& hi) {
    asm("mov.b64 {%0, %1}, %2;" : "=f"(lo), "=f"(hi) : "l"(v));
}
__device__ __forceinline__ unsigned long long ffma2(unsigned long long a,
                                                    unsigned long long b,
                                                    unsigned long long c) {
    unsigned long long d;
    asm("fma.rn.f32x2 %0, %1, %2, %3;" : "=l"(d) : "l"(a), "l"(b), "l"(c));
    return d;
}
__device__ __forceinline__ unsigned long long fmul2(unsigned long long a,
                                                    unsigned long long b) {
    unsigned long long d;
    asm("mul.rn.f32x2 %0, %1, %2;" : "=l"(d) : "l"(a), "l"(b));
    return d;
}

// ---------------- JAX partitionable threefry (key = (0, 42)) ----------------
// jax_threefry_partitionable=True (default in modern JAX):
//   bits[i] = y0 ^ y1, where (y0,y1) = threefry2x32((0,42), (hi32(i), lo32(i))).
// Mask size = 2^27 < 2^32, so hi32(i) = 0 always.
// keep <=> uniform(bits) < 0.9f <=> (bits >> 9) < mantissa(1.9f) <=> bits < 0xE6666600.
__device__ __forceinline__ uint32_t tf32_hash(uint32_t idx) {
    const uint32_t ks1 = 42u;
    const uint32_t ks2 = 42u ^ 0x1BD11BDAu;   // 0x1BD11BF0
    uint32_t x0 = 0u;           // hi counter (0) + ks0 (0)
    uint32_t x1 = idx + ks1;    // lo counter + ks1
#define TFR(r) { x0 += x1; x1 = __funnelshift_l(x1, x1, (r)); x1 ^= x0; }
    TFR(13) TFR(15) TFR(26) TFR(6)
    x0 += ks1; x1 += ks2 + 1u;
    TFR(17) TFR(29) TFR(16) TFR(24)
    x0 += ks2; x1 += 2u;
    TFR(13) TFR(15) TFR(26) TFR(6)
    /* x0 += ks0 (=0) */ x1 += ks1 + 3u;
    TFR(17) TFR(29) TFR(16) TFR(24)
    x0 += ks1; x1 += ks2 + 4u;
    TFR(13) TFR(15) TFR(26) TFR(6)
    x0 += ks2; x1 += 5u;
#undef TFR
    return x0 ^ x1;
}

#define KEEP_THRESH 0xE6666600u

// ---------------- fused attention kernel ----------------
// One block: one head h, one 64-query tile, BOTH batches (shares K/V smem).
// 256 threads as 16x16; each thread owns a 4q x 4k score microtile and a
// 4q x 4dv output microtile, per batch.
__global__ void __launch_bounds__(NT) attn_kernel(
    const float* __restrict__ q_g,
    const float* __restrict__ k_g,
    const float* __restrict__ v_g,
    float* __restrict__ out_g)
{
    extern __shared__ float smem[];
    float4* Qs4 = reinterpret_cast<float4*>(smem + SM_Q);
    float4* Ks4 = reinterpret_cast<float4*>(smem + SM_K);
    float4* Vs4 = reinterpret_cast<float4*>(smem + SM_V);
    float*  Ps  = smem + SM_P;
    float4* Ps4 = reinterpret_cast<float4*>(Ps);

    const int tid = threadIdx.x;
    const int tx  = tid & 15;
    const int ty  = tid >> 4;
    const int h   = blockIdx.y;
    const int q0  = blockIdx.x * TQ;

    // ---- load Q tiles (both batches), rows padded to 68 floats ----
    {
        const float4* qg4 = reinterpret_cast<const float4*>(q_g);
        #pragma unroll
        for (int it = 0; it < 8; ++it) {
            int idx = tid + it * NT;          // 0..2047
            int b   = idx >> 10;
            int r   = (idx >> 4) & 63;
            int d4  = idx & 15;
            Qs4[(b * 64 + r) * QROW4 + d4] =
                qg4[((b * KH + h) * KSQ + q0 + r) * 16 + d4];
        }
    }

    float m[2][4], l[2][4];
    unsigned long long O2[2][4][2];   // packed dv-pair accumulators
    #pragma unroll
    for (int b = 0; b < 2; ++b)
    #pragma unroll
    for (int i = 0; i < 4; ++i) {
        m[b][i] = -INFINITY;
        l[b][i] = 0.f;
        O2[b][i][0] = 0ull;
        O2[b][i][1] = 0ull;
    }

    const float4* kg4 = reinterpret_cast<const float4*>(k_g);
    const float4* vg4 = reinterpret_cast<const float4*>(v_g);

    for (int kt = 0; kt < KSK / TK; ++kt) {
        __syncthreads();
        // ---- load K (XOR-swizzled to kill LDS bank conflicts) and V ----
        #pragma unroll
        for (int it = 0; it < 4; ++it) {
            int idx = tid + it * NT;          // 0..1023
            int r   = idx >> 4;
            int d4  = idx & 15;
            int g   = (h * KSK + kt * TK + r) * 16 + d4;
            Ks4[r * 16 + (d4 ^ (r >> 2))] = kg4[g];
            Vs4[idx] = vg4[g];
        }
        __syncthreads();

        // ---- S = Q K^T, packed over d-parity (free packing from float4) ----
        unsigned long long s2[2][4][4];
        #pragma unroll
        for (int b = 0; b < 2; ++b)
        #pragma unroll
        for (int i = 0; i < 4; ++i)
        #pragma unroll
        for (int j = 0; j < 4; ++j) s2[b][i][j] = 0ull;

        #pragma unroll
        for (int d4 = 0; d4 < 16; ++d4) {
            unsigned long long k01[4], k23[4];
            #pragma unroll
            for (int j = 0; j < 4; ++j) {
                float4 kv = Ks4[(tx * 4 + j) * 16 + (d4 ^ tx)];
                k01[j] = pk2(kv.x, kv.y);
                k23[j] = pk2(kv.z, kv.w);
            }
            #pragma unroll
            for (int b = 0; b < 2; ++b)
            #pragma unroll
            for (int i = 0; i < 4; ++i) {
                float4 qv = Qs4[(b * 64 + ty * 4 + i) * QROW4 + d4];
                unsigned long long q01 = pk2(qv.x, qv.y);
                unsigned long long q23 = pk2(qv.z, qv.w);
                #pragma unroll
                for (int j = 0; j < 4; ++j) {
                    s2[b][i][j] = ffma2(q01, k01[j], s2[b][i][j]);
                    s2[b][i][j] = ffma2(q23, k23[j], s2[b][i][j]);
                }
            }
        }

        // ---- online softmax update (row owned by 16 tx-lanes) ----
        float s[2][4][4];
        #pragma unroll
        for (int b = 0; b < 2; ++b)
        #pragma unroll
        for (int i = 0; i < 4; ++i) {
            #pragma unroll
            for (int j = 0; j < 4; ++j) {
                float lo, hi; upk2(s2[b][i][j], lo, hi);
                s[b][i][j] = lo + hi;
            }
            float mloc = fmaxf(fmaxf(s[b][i][0], s[b][i][1]),
                               fmaxf(s[b][i][2], s[b][i][3]));
            #pragma unroll
            for (int off = 8; off > 0; off >>= 1)
                mloc = fmaxf(mloc, __shfl_xor_sync(0xffffffffu, mloc, off));
            float mnew = fmaxf(m[b][i], mloc);
            float corr = __expf(m[b][i] - mnew);
            float ps = 0.f;
            #pragma unroll
            for (int j = 0; j < 4; ++j) {
                float p = __expf(s[b][i][j] - mnew);
                s[b][i][j] = p;
                ps += p;
            }
            #pragma unroll
            for (int off = 8; off > 0; off >>= 1)
                ps += __shfl_xor_sync(0xffffffffu, ps, off);
            l[b][i] = l[b][i] * corr + ps;
            m[b][i] = mnew;
            unsigned long long cc = pk2(corr, corr);
            O2[b][i][0] = fmul2(O2[b][i][0], cc);
            O2[b][i][1] = fmul2(O2[b][i][1], cc);
        }

        // ---- JAX partitionable-threefry dropout (one hash per element) ----
        #pragma unroll
        for (int i = 0; i < 4; ++i) {
            uint32_t rowg = (uint32_t)(h * KSQ + q0 + ty * 4 + i);
            #pragma unroll
            for (int j = 0; j < 4; ++j) {
                uint32_t idx0 = (rowg << 11) | (uint32_t)(kt * TK + tx * 4 + j);
                uint32_t b0 = tf32_hash(idx0);
                uint32_t b1 = tf32_hash(idx0 + 0x04000000u);  // batch 1
                float p0 = (b0 < KEEP_THRESH) ? s[0][i][j] : 0.f;
                float p1 = (b1 < KEEP_THRESH) ? s[1][i][j] : 0.f;
                int prow = (ty * 4 + i) * 68 + tx * 4 + j;
                Ps[prow] = p0;
                Ps[64 * 68 + prow] = p1;
            }
        }
        __syncthreads();

        // ---- O += P V (packed over dv pairs, p duplicated per scalar) ----
        #pragma unroll
        for (int k4 = 0; k4 < 16; ++k4) {
            unsigned long long v01[4], v23[4];
            #pragma unroll
            for (int kk = 0; kk < 4; ++kk) {
                float4 vv = Vs4[(k4 * 4 + kk) * 16 + tx];
                v01[kk] = pk2(vv.x, vv.y);
                v23[kk] = pk2(vv.z, vv.w);
            }
            #pragma unroll
            for (int b = 0; b < 2; ++b)
            #pragma unroll
            for (int i = 0; i < 4; ++i) {
                float4 pv = Ps4[(b * 64 + ty * 4 + i) * QROW4 + k4];
                unsigned long long pp;
                pp = pk2(pv.x, pv.x);
                O2[b][i][0] = ffma2(pp, v01[0], O2[b][i][0]);
                O2[b][i][1] = ffma2(pp, v23[0], O2[b][i][1]);
                pp = pk2(pv.y, pv.y);
                O2[b][i][0] = ffma2(pp, v01[1], O2[b][i][0]);
                O2[b][i][1] = ffma2(pp, v23[1], O2[b][i][1]);
                pp = pk2(pv.z, pv.z);
                O2[b][i][0] = ffma2(pp, v01[2], O2[b][i][0]);
                O2[b][i][1] = ffma2(pp, v23[2], O2[b][i][1]);
                pp = pk2(pv.w, pv.w);
                O2[b][i][0] = ffma2(pp, v01[3], O2[b][i][0]);
                O2[b][i][1] = ffma2(pp, v23[3], O2[b][i][1]);
            }
        }
    }

    // ---- epilogue: out = acc * (inv_scale / keep_prob) / l ----
    const float fin = 0.5f / 0.9f;
    float4* out4 = reinterpret_cast<float4*>(out_g);
    #pragma unroll
    for (int b = 0; b < 2; ++b)
    #pragma unroll
    for (int i = 0; i < 4; ++i) {
        float sc = fin / l[b][i];
        float o0, o1, o2, o3;
        upk2(O2[b][i][0], o0, o1);
        upk2(O2[b][i][1], o2, o3);
        out4[((b * KH + h) * KSQ + q0 + ty * 4 + i) * 16 + tx] =
            make_float4(o0 * sc, o1 * sc, o2 * sc, o3 * sc);
    }
}

extern "C" void kernel_launch(void* const* d_in, const int* in_sizes, int n_in,
                              void* d_out, int out_size) {
    (void)in_sizes; (void)n_in; (void)out_size;
    const float* q = (const float*)d_in[0];
    const float* k = (const float*)d_in[1];
    const float* v = (const float*)d_in[2];
    float* out = (float*)d_out;

    size_t smem_bytes = SM_TOTAL_FLOATS * sizeof(float);   // 102400 B
    cudaFuncSetAttribute(attn_kernel,
                         cudaFuncAttributeMaxDynamicSharedMemorySize,
                         (int)smem_bytes);
    dim3 grid(KSQ / TQ, KH);   // (32, 16): one block per (q-tile, head), both batches
    attn_kernel<<<grid, NT, smem_bytes>>>(q, k, v, out);
}

// round 3
// speedup vs baseline: 1.1614x; 1.1614x over previous
#include <cuda_runtime.h>
#include <cstdint>
#include <math.h>

// Problem constants
#define KB  2
#define KH  16
#define KSQ 2048
#define KSK 2048
#define KD  64
#define KDV 64

#define TQ 64
#define TK 64
#define NT 256
#define QROW4 17   // padded row stride (in float4) for Q and P tiles = 68 floats

// smem layout (floats): Q [64][68] = 4352 | K [64][16f4 swizzled] = 4096
//                       V [64][16f4] = 4096 | P [64][68] = 4352
#define SM_Q 0
#define SM_K 4352
#define SM_V 8448
#define SM_P 12544
#define SM_TOTAL_FLOATS 16896   // 67584 bytes

// ---------------- packed f32x2 helpers (sm_103a FFMA2 path) ----------------
__device__ __forceinline__ unsigned long long pk2(float lo, float hi) {
    unsigned long long r;
    asm("mov.b64 %0, {%1, %2};" : "=l"(r) : "f"(lo), "f"(hi));
    return r;
}
__device__ __forceinline__ void upk2(unsigned long long v, float& lo, float& hi) {
    asm("mov.b64 {%0, %1}, %2;" : "=f"(lo), "=f"(hi) : "l"(v));
}
__device__ __forceinline__ unsigned long long ffma2(unsigned long long a,
                                                    unsigned long long b,
                                                    unsigned long long c) {
    unsigned long long d;
    asm("fma.rn.f32x2 %0, %1, %2, %3;" : "=l"(d) : "l"(a), "l"(b), "l"(c));
    return d;
}
__device__ __forceinline__ unsigned long long fmul2(unsigned long long a,
                                                    unsigned long long b) {
    unsigned long long d;
    asm("mul.rn.f32x2 %0, %1, %2;" : "=l"(d) : "l"(a), "l"(b));
    return d;
}

// ---------------- JAX partitionable threefry (key = (0, 42)) ----------------
//   bits[i] = y0 ^ y1, (y0,y1) = threefry2x32((0,42), (0, i))   [i < 2^27]
// keep <=> bits < 0xE6666600  (== uniform(bits) < 0.9f)
__device__ __forceinline__ uint32_t tf32_hash(uint32_t idx) {
    const uint32_t ks1 = 42u;
    const uint32_t ks2 = 42u ^ 0x1BD11BDAu;   // 0x1BD11BF0
    uint32_t x0 = 0u;
    uint32_t x1 = idx + ks1;
#define TFR(r) { x0 += x1; x1 = __funnelshift_l(x1, x1, (r)); x1 ^= x0; }
    TFR(13) TFR(15) TFR(26) TFR(6)
    x0 += ks1; x1 += ks2 + 1u;
    TFR(17) TFR(29) TFR(16) TFR(24)
    x0 += ks2; x1 += 2u;
    TFR(13) TFR(15) TFR(26) TFR(6)
    x1 += ks1 + 3u;
    TFR(17) TFR(29) TFR(16) TFR(24)
    x0 += ks1; x1 += ks2 + 4u;
    TFR(13) TFR(15) TFR(26) TFR(6)
    x0 += ks2; x1 += 5u;
#undef TFR
    return x0 ^ x1;
}

#define KEEP_THRESH 0xE6666600u

// ---------------- fused attention kernel ----------------
// One block: one (batch, head, 64-query tile). 256 threads as 16x16;
// each thread owns a 4q x 4k score microtile and a 4q x 4dv output microtile.
__global__ void __launch_bounds__(NT, 2) attn_kernel(
    const float* __restrict__ q_g,
    const float* __restrict__ k_g,
    const float* __restrict__ v_g,
    float* __restrict__ out_g)
{
    extern __shared__ float smem[];
    float4* Qs4 = reinterpret_cast<float4*>(smem + SM_Q);
    float4* Ks4 = reinterpret_cast<float4*>(smem + SM_K);
    float4* Vs4 = reinterpret_cast<float4*>(smem + SM_V);
    float*  Ps  = smem + SM_P;
    float4* Ps4 = reinterpret_cast<float4*>(Ps);

    const int tid = threadIdx.x;
    const int tx  = tid & 15;
    const int ty  = tid >> 4;
    const int h   = blockIdx.y;
    const int b   = blockIdx.z;
    const int q0  = blockIdx.x * TQ;

    // ---- load Q tile, rows padded to 68 floats ----
    {
        const float4* qg4 = reinterpret_cast<const float4*>(q_g);
        #pragma unroll
        for (int it = 0; it < 4; ++it) {
            int idx = tid + it * NT;          // 0..1023
            int r   = idx >> 4;
            int d4  = idx & 15;
            Qs4[r * QROW4 + d4] = qg4[((b * KH + h) * KSQ + q0 + r) * 16 + d4];
        }
    }

    float m[4], l[4];
    unsigned long long O2[4][2];   // packed dv-pair accumulators
    #pragma unroll
    for (int i = 0; i < 4; ++i) {
        m[i] = -INFINITY;
        l[i] = 0.f;
        O2[i][0] = 0ull;
        O2[i][1] = 0ull;
    }

    const float4* kg4 = reinterpret_cast<const float4*>(k_g);
    const float4* vg4 = reinterpret_cast<const float4*>(v_g);
    const uint32_t bbase = (uint32_t)b << 26;

    for (int kt = 0; kt < KSK / TK; ++kt) {
        __syncthreads();
        // ---- load K (XOR-swizzled to kill LDS bank conflicts) and V ----
        #pragma unroll
        for (int it = 0; it < 4; ++it) {
            int idx = tid + it * NT;          // 0..1023
            int r   = idx >> 4;
            int d4  = idx & 15;
            int g   = (h * KSK + kt * TK + r) * 16 + d4;
            Ks4[r * 16 + (d4 ^ (r >> 2))] = kg4[g];
            Vs4[idx] = vg4[g];
        }
        __syncthreads();

        // ---- S = Q K^T, packed over d-parity (free packing from float4) ----
        unsigned long long s2[4][4];
        #pragma unroll
        for (int i = 0; i < 4; ++i)
        #pragma unroll
        for (int j = 0; j < 4; ++j) s2[i][j] = 0ull;

        #pragma unroll
        for (int d4 = 0; d4 < 16; ++d4) {
            unsigned long long k01[4], k23[4];
            #pragma unroll
            for (int j = 0; j < 4; ++j) {
                float4 kv = Ks4[(tx * 4 + j) * 16 + (d4 ^ tx)];
                k01[j] = pk2(kv.x, kv.y);
                k23[j] = pk2(kv.z, kv.w);
            }
            #pragma unroll
            for (int i = 0; i < 4; ++i) {
                float4 qv = Qs4[(ty * 4 + i) * QROW4 + d4];
                unsigned long long q01 = pk2(qv.x, qv.y);
                unsigned long long q23 = pk2(qv.z, qv.w);
                #pragma unroll
                for (int j = 0; j < 4; ++j) {
                    s2[i][j] = ffma2(q01, k01[j], s2[i][j]);
                    s2[i][j] = ffma2(q23, k23[j], s2[i][j]);
                }
            }
        }

        // ---- online softmax update (row owned by 16 tx-lanes) ----
        float s[4][4];
        #pragma unroll
        for (int i = 0; i < 4; ++i) {
            #pragma unroll
            for (int j = 0; j < 4; ++j) {
                float lo, hi; upk2(s2[i][j], lo, hi);
                s[i][j] = lo + hi;
            }
            float mloc = fmaxf(fmaxf(s[i][0], s[i][1]),
                               fmaxf(s[i][2], s[i][3]));
            #pragma unroll
            for (int off = 8; off > 0; off >>= 1)
                mloc = fmaxf(mloc, __shfl_xor_sync(0xffffffffu, mloc, off));
            float mnew = fmaxf(m[i], mloc);
            float corr = __expf(m[i] - mnew);
            float ps = 0.f;
            #pragma unroll
            for (int j = 0; j < 4; ++j) {
                float p = __expf(s[i][j] - mnew);
                s[i][j] = p;
                ps += p;
            }
            #pragma unroll
            for (int off = 8; off > 0; off >>= 1)
                ps += __shfl_xor_sync(0xffffffffu, ps, off);
            l[i] = l[i] * corr + ps;
            m[i] = mnew;
            unsigned long long cc = pk2(corr, corr);
            O2[i][0] = fmul2(O2[i][0], cc);
            O2[i][1] = fmul2(O2[i][1], cc);
        }

        // ---- JAX partitionable-threefry dropout (one hash per element) ----
        #pragma unroll
        for (int i = 0; i < 4; ++i) {
            uint32_t rowg = (uint32_t)(h * KSQ + q0 + ty * 4 + i);
            uint32_t base = bbase | (rowg << 11) | (uint32_t)(kt * TK + tx * 4);
            #pragma unroll
            for (int j = 0; j < 4; ++j) {
                uint32_t bits = tf32_hash(base + (uint32_t)j);
                Ps[(ty * 4 + i) * 68 + tx * 4 + j] =
                    (bits < KEEP_THRESH) ? s[i][j] : 0.f;
            }
        }
        __syncthreads();

        // ---- O += P V (packed over dv pairs, p duplicated per scalar) ----
        #pragma unroll
        for (int k4 = 0; k4 < 16; ++k4) {
            unsigned long long v01[4], v23[4];
            #pragma unroll
            for (int kk = 0; kk < 4; ++kk) {
                float4 vv = Vs4[(k4 * 4 + kk) * 16 + tx];
                v01[kk] = pk2(vv.x, vv.y);
                v23[kk] = pk2(vv.z, vv.w);
            }
            #pragma unroll
            for (int i = 0; i < 4; ++i) {
                float4 pv = Ps4[(ty * 4 + i) * QROW4 + k4];
                unsigned long long pp;
                pp = pk2(pv.x, pv.x);
                O2[i][0] = ffma2(pp, v01[0], O2[i][0]);
                O2[i][1] = ffma2(pp, v23[0], O2[i][1]);
                pp = pk2(pv.y, pv.y);
                O2[i][0] = ffma2(pp, v01[1], O2[i][0]);
                O2[i][1] = ffma2(pp, v23[1], O2[i][1]);
                pp = pk2(pv.z, pv.z);
                O2[i][0] = ffma2(pp, v01[2], O2[i][0]);
                O2[i][1] = ffma2(pp, v23[2], O2[i][1]);
                pp = pk2(pv.w, pv.w);
                O2[i][0] = ffma2(pp, v01[3], O2[i][0]);
                O2[i][1] = ffma2(pp, v23[3], O2[i][1]);
            }
        }
    }

    // ---- epilogue: out = acc * (inv_scale / keep_prob) / l ----
    const float fin = 0.5f / 0.9f;
    float4* out4 = reinterpret_cast<float4*>(out_g);
    #pragma unroll
    for (int i = 0; i < 4; ++i) {
        float sc = fin / l[i];
        float o0, o1, o2, o3;
        upk2(O2[i][0], o0, o1);
        upk2(O2[i][1], o2, o3);
        out4[((b * KH + h) * KSQ + q0 + ty * 4 + i) * 16 + tx] =
            make_float4(o0 * sc, o1 * sc, o2 * sc, o3 * sc);
    }
}

extern "C" void kernel_launch(void* const* d_in, const int* in_sizes, int n_in,
                              void* d_out, int out_size) {
    (void)in_sizes; (void)n_in; (void)out_size;
    const float* q = (const float*)d_in[0];
    const float* k = (const float*)d_in[1];
    const float* v = (const float*)d_in[2];
    float* out = (float*)d_out;

    size_t smem_bytes = SM_TOTAL_FLOATS * sizeof(float);   // 67584 B
    cudaFuncSetAttribute(attn_kernel,
                         cudaFuncAttributeMaxDynamicSharedMemorySize,
                         (int)smem_bytes);
    dim3 grid(KSQ / TQ, KH, KB);   // (32, 16, 2)
    attn_kernel<<<grid, NT, smem_bytes>>>(q, k, v, out);
}